// round 8
// baseline (speedup 1.0000x reference)
#include <cuda_runtime.h>
#include <cuda.h>
#include <math.h>

// Top2Router: x[16384,2048] fp32, W[8,2048], b[8]
// out (fp32 concat): top2_val[N*2] | top2_idx[N*2] | gate[N*8]
//
// R7 TMA kernel + untracked L2 tensor prefetch (distance 8 chunks) to break
// the per-SM outstanding-miss cap: demand TMA hits L2, DRAM driven by the
// fire-and-forget prefetch stream.

#define D_MODEL  2048
#define NEXP     8
#define KCHUNK   64
#define NCHUNK   (D_MODEL / KCHUNK)   // 32
#define NSTAGE   5
#define THREADS  512
#define NWARP    16
#define PFDIST   8                     // L2 prefetch distance (chunks)

typedef unsigned long long u64;

__device__ __forceinline__ void mbar_init(unsigned mb, unsigned count) {
    asm volatile("mbarrier.init.shared.b64 [%0], %1;" :: "r"(mb), "r"(count) : "memory");
}
__device__ __forceinline__ void mbar_expect_tx(unsigned mb, unsigned bytes) {
    asm volatile("mbarrier.arrive.expect_tx.shared.b64 _, [%0], %1;"
                 :: "r"(mb), "r"(bytes) : "memory");
}
__device__ __forceinline__ void mbar_wait(unsigned mb, unsigned parity) {
    asm volatile(
        "{\n\t.reg .pred P;\n"
        "W_%=:\n\t"
        "mbarrier.try_wait.parity.acquire.cta.shared::cta.b64 P, [%0], %1, 0x989680;\n\t"
        "@P bra D_%=;\n\t"
        "bra W_%=;\n"
        "D_%=:\n\t}"
        :: "r"(mb), "r"(parity) : "memory");
}
__device__ __forceinline__ void tma2d(unsigned dst, const CUtensorMap* map,
                                      int c0, int c1, unsigned mb) {
    asm volatile(
        "cp.async.bulk.tensor.2d.shared::cta.global.tile.mbarrier::complete_tx::bytes "
        "[%0], [%1, {%2, %3}], [%4];"
        :: "r"(dst), "l"(map), "r"(c0), "r"(c1), "r"(mb) : "memory");
}
__device__ __forceinline__ void tma2d_prefetch_l2(const CUtensorMap* map,
                                                  int c0, int c1) {
    asm volatile(
        "cp.async.bulk.prefetch.tensor.2d.L2.global.tile [%0, {%1, %2}];"
        :: "l"(map), "r"(c0), "r"(c1) : "memory");
}

__global__ __launch_bounds__(THREADS, 1)
void top2_router_kernel(const __grid_constant__ CUtensorMap mapHi,
                        const __grid_constant__ CUtensorMap mapLo,
                        const float* __restrict__ W,
                        const float* __restrict__ b,
                        float* __restrict__ out,
                        int n_tok, int hi)
{
    extern __shared__ float smem[];
    const int stageFloats = 64 * hi;            // 2 tiles * 32 * hi
    const int ringFloats  = NSTAGE * stageFloats;
    float* ring = smem;
    float* wt   = smem + ringFloats;

    const unsigned smem_u32 = (unsigned)__cvta_generic_to_shared(smem);
    const unsigned ring_u32 = smem_u32;
    const unsigned mbar0    = smem_u32 + (unsigned)(ringFloats + 16384) * 4u;
    const unsigned stageBytes = (unsigned)stageFloats * 4u;
    const unsigned tileBytes  = (unsigned)(32 * hi) * 4u;

    const int tid  = threadIdx.x;
    const int w    = tid >> 5;
    const int lane = tid & 31;

    // balanced token range (units of 8 tokens)
    const int G     = gridDim.x;
    const int units = n_tok >> 3;
    const int s8    = (int)(((long long)blockIdx.x       * units) / G);
    const int e8    = (int)(((long long)(blockIdx.x + 1) * units) / G);
    const int tokenBase = s8 * 8;
    const int ntok_b    = (e8 - s8) * 8;        // hi or hi-8

    const CUtensorMap* mp = (ntok_b == hi) ? &mapHi : &mapLo;
    const unsigned chunkBytes = (unsigned)ntok_b * 256u;

    // ---- stage W transposed: wt[k*8+e] = W[e*2048+k]
    #pragma unroll
    for (int i = 0; i < (D_MODEL * NEXP) / THREADS; ++i) {   // 32
        int idx = tid + i * THREADS;
        int e = idx >> 11;
        int k = idx & (D_MODEL - 1);
        wt[k * NEXP + e] = W[idx];
    }
    if (tid == 0) {
        #pragma unroll
        for (int s = 0; s < NSTAGE; ++s) mbar_init(mbar0 + s * 8, 1);
    }
    __syncthreads();

    const u64* wt64 = reinterpret_cast<const u64*>(wt);

    u64 acc[4][4];
    #pragma unroll
    for (int t = 0; t < 4; ++t)
        #pragma unroll
        for (int p = 0; p < 4; ++p) acc[t][p] = 0ull;

    // prologue: L2-prefetch chunks 0..PFDIST-1, then TMA-issue chunks 0..2
    if (tid == 0) {
        #pragma unroll
        for (int c = 0; c < PFDIST; ++c) {
            tma2d_prefetch_l2(mp, c * KCHUNK,      tokenBase);
            tma2d_prefetch_l2(mp, c * KCHUNK + 32, tokenBase);
        }
        #pragma unroll
        for (int c = 0; c < 3; ++c) {
            unsigned mb  = mbar0 + (c % NSTAGE) * 8;
            unsigned dst = ring_u32 + (unsigned)(c % NSTAGE) * stageBytes;
            mbar_expect_tx(mb, chunkBytes);
            tma2d(dst,             mp, c * KCHUNK,      tokenBase, mb);
            tma2d(dst + tileBytes, mp, c * KCHUNK + 32, tokenBase, mb);
        }
    }

    const int ws7    = w & 7;
    const int tsel   = (w >> 3);                // tile 0/1 (k<32 / k>=32)
    const int tokLim = ntok_b - 1;

    for (int c = 0; c < NCHUNK; ++c) {
        if (tid == 0) {
            if (c + PFDIST < NCHUNK) {
                tma2d_prefetch_l2(mp, (c + PFDIST) * KCHUNK,      tokenBase);
                tma2d_prefetch_l2(mp, (c + PFDIST) * KCHUNK + 32, tokenBase);
            }
            if (c + 3 < NCHUNK) {
                int cc = c + 3;
                unsigned mb  = mbar0 + (cc % NSTAGE) * 8;
                unsigned dst = ring_u32 + (unsigned)(cc % NSTAGE) * stageBytes;
                mbar_expect_tx(mb, chunkBytes);
                tma2d(dst,             mp, cc * KCHUNK,      tokenBase, mb);
                tma2d(dst + tileBytes, mp, cc * KCHUNK + 32, tokenBase, mb);
            }
        }
        mbar_wait(mbar0 + (c % NSTAGE) * 8, (unsigned)((c / NSTAGE) & 1));
        __syncthreads();

        const float* tile = ring + (c % NSTAGE) * stageFloats + tsel * (32 * hi);

        float4 xv[4];
        #pragma unroll
        for (int t = 0; t < 4; ++t) {
            int tok = lane + t * 32;
            int tokc = tok > tokLim ? tokLim : tok;
            xv[t] = reinterpret_cast<const float4*>(tile + tokc * 32)
                        [ws7 ^ (tokc & 7)];
        }

        #pragma unroll
        for (int j = 0; j < 4; ++j) {
            int kg = c * KCHUNK + w * 4 + j;
            u64 wp0 = wt64[kg * 4 + 0];
            u64 wp1 = wt64[kg * 4 + 1];
            u64 wp2 = wt64[kg * 4 + 2];
            u64 wp3 = wt64[kg * 4 + 3];
            #pragma unroll
            for (int t = 0; t < 4; ++t) {
                float xk = (j == 0) ? xv[t].x : (j == 1) ? xv[t].y
                         : (j == 2) ? xv[t].z : xv[t].w;
                u64 xx;
                asm("mov.b64 %0, {%1, %1};" : "=l"(xx) : "f"(xk));
                asm("fma.rn.f32x2 %0, %1, %2, %0;" : "+l"(acc[t][0]) : "l"(xx), "l"(wp0));
                asm("fma.rn.f32x2 %0, %1, %2, %0;" : "+l"(acc[t][1]) : "l"(xx), "l"(wp1));
                asm("fma.rn.f32x2 %0, %1, %2, %0;" : "+l"(acc[t][2]) : "l"(xx), "l"(wp2));
                asm("fma.rn.f32x2 %0, %1, %2, %0;" : "+l"(acc[t][3]) : "l"(xx), "l"(wp3));
            }
        }
    }
    __syncthreads();

    // ---- cross-warp reduction (reuse ring)
    float2* red = reinterpret_cast<float2*>(ring);
    #pragma unroll
    for (int t = 0; t < 4; ++t) {
        int tok = lane + t * 32;
        #pragma unroll
        for (int p = 0; p < 4; ++p) {
            float lo, hv;
            asm("mov.b64 {%0, %1}, %2;" : "=f"(lo), "=f"(hv) : "l"(acc[t][p]));
            red[(w * 128 + tok) * 4 + p] = make_float2(lo, hv);
        }
    }
    __syncthreads();

    float* lgs = ring + 16384;
    {
        int tok = tid >> 2;
        int p   = tid & 3;
        float2 s = make_float2(0.f, 0.f);
        #pragma unroll
        for (int ww = 0; ww < NWARP; ++ww) {
            float2 v = red[(ww * 128 + tok) * 4 + p];
            s.x += v.x; s.y += v.y;
        }
        s.x += b[2 * p];
        s.y += b[2 * p + 1];
        reinterpret_cast<float2*>(lgs)[tok * 4 + p] = s;
    }
    __syncthreads();

    // ---- per-token softmax + stable top2
    if (tid < ntok_b) {
        const int g = tokenBase + tid;
        float gv[NEXP];
        float mx = -INFINITY;
        #pragma unroll
        for (int e = 0; e < NEXP; ++e) {
            gv[e] = lgs[tid * NEXP + e];
            mx = fmaxf(mx, gv[e]);
        }
        float ssum = 0.f;
        #pragma unroll
        for (int e = 0; e < NEXP; ++e) {
            gv[e] = __expf(gv[e] - mx);
            ssum += gv[e];
        }
        float inv = 1.f / ssum;
        #pragma unroll
        for (int e = 0; e < NEXP; ++e) gv[e] *= inv;

        float* gate_out = out + (size_t)n_tok * 4;
        float4 g0 = make_float4(gv[0], gv[1], gv[2], gv[3]);
        float4 g1 = make_float4(gv[4], gv[5], gv[6], gv[7]);
        *reinterpret_cast<float4*>(gate_out + (size_t)g * NEXP)     = g0;
        *reinterpret_cast<float4*>(gate_out + (size_t)g * NEXP + 4) = g1;

        int i1 = 0; float v1 = gv[0];
        #pragma unroll
        for (int e = 1; e < NEXP; ++e)
            if (gv[e] > v1) { v1 = gv[e]; i1 = e; }
        int i2 = -1; float v2 = -INFINITY;
        #pragma unroll
        for (int e = 0; e < NEXP; ++e)
            if (e != i1 && gv[e] > v2) { v2 = gv[e]; i2 = e; }

        *reinterpret_cast<float2*>(out + (size_t)g * 2) = make_float2(v1, v2);
        float* idx_out = out + (size_t)n_tok * 2;
        *reinterpret_cast<float2*>(idx_out + (size_t)g * 2) =
            make_float2((float)i1, (float)i2);
    }
}

// ---------------------------------------------------------------------------

typedef CUresult (*EncodeTiledFn)(
    CUtensorMap*, CUtensorMapDataType, cuuint32_t, void*,
    const cuuint64_t*, const cuuint64_t*, const cuuint32_t*, const cuuint32_t*,
    CUtensorMapInterleave, CUtensorMapSwizzle, CUtensorMapL2promotion,
    CUtensorMapFloatOOBfill);

static CUtensorMap g_mapHi, g_mapLo;
static const void* g_last_x = nullptr;
static int g_nsm = 0, g_hi = 0, g_smem = 0;

static void build_maps(const float* x, int n_tok, int hi, int lo)
{
    EncodeTiledFn enc = nullptr;
    cudaDriverEntryPointQueryResult qr;
    cudaGetDriverEntryPoint("cuTensorMapEncodeTiled", (void**)&enc,
                            cudaEnableDefault, &qr);
    cuuint64_t dims[2]    = {(cuuint64_t)D_MODEL, (cuuint64_t)n_tok};
    cuuint64_t strides[1] = {(cuuint64_t)D_MODEL * 4};
    cuuint32_t elem[2]    = {1, 1};
    cuuint32_t boxH[2]    = {32, (cuuint32_t)hi};
    cuuint32_t boxL[2]    = {32, (cuuint32_t)lo};
    enc(&g_mapHi, CU_TENSOR_MAP_DATA_TYPE_FLOAT32, 2, (void*)x,
        dims, strides, boxH, elem,
        CU_TENSOR_MAP_INTERLEAVE_NONE, CU_TENSOR_MAP_SWIZZLE_128B,
        CU_TENSOR_MAP_L2_PROMOTION_L2_128B, CU_TENSOR_MAP_FLOAT_OOB_FILL_NONE);
    enc(&g_mapLo, CU_TENSOR_MAP_DATA_TYPE_FLOAT32, 2, (void*)x,
        dims, strides, boxL, elem,
        CU_TENSOR_MAP_INTERLEAVE_NONE, CU_TENSOR_MAP_SWIZZLE_128B,
        CU_TENSOR_MAP_L2_PROMOTION_L2_128B, CU_TENSOR_MAP_FLOAT_OOB_FILL_NONE);
}

extern "C" void kernel_launch(void* const* d_in, const int* in_sizes, int n_in,
                              void* d_out, int out_size)
{
    const float* x = (const float*)d_in[0];
    const float* W = (const float*)d_in[1];
    const float* b = (const float*)d_in[2];
    float* out = (float*)d_out;

    const int n_tok = in_sizes[0] / D_MODEL;     // 16384

    if (g_nsm == 0) {
        cudaDeviceProp prop;
        cudaGetDeviceProperties(&prop, 0);
        g_nsm = prop.multiProcessorCount;        // 152 on GB300
        int units = n_tok >> 3;
        int hiU = (units + g_nsm - 1) / g_nsm;
        int loU = units / g_nsm;
        g_hi = hiU * 8;
        int lo = (loU > 0 ? loU : 1) * 8;
        g_smem = (NSTAGE * 64 * g_hi + 16384) * 4 + 64;
        cudaFuncSetAttribute(top2_router_kernel,
                             cudaFuncAttributeMaxDynamicSharedMemorySize, g_smem);
        build_maps(x, n_tok, g_hi, lo);
        g_last_x = x;
    } else if (g_last_x != x) {
        int units = n_tok >> 3;
        int loU = units / g_nsm;
        build_maps(x, n_tok, g_hi, (loU > 0 ? loU : 1) * 8);
        g_last_x = x;
    }

    top2_router_kernel<<<g_nsm, THREADS, g_smem>>>(g_mapHi, g_mapLo,
                                                   W, b, out, n_tok, g_hi);
}

// round 9
// speedup vs baseline: 1.0018x; 1.0018x over previous
#include <cuda_runtime.h>
#include <math.h>

// Top2Router: x[16384,2048] fp32, W[8,2048], b[8]
// out (fp32 concat): top2_val[N*2] | top2_idx[N*2] | gate[N*8]
//
// Sequential-granularity streaming:
//  - grid=#SMs, 512 thr. Block owns balanced contiguous token range (mult 8).
//  - Warp processes passes of 4 tokens. Per k-group (128 floats) the warp
//    reads 512B CONTIGUOUS from each of its 4 rows (lane l -> float4 at 4l),
//    cycling rows -> DRAM sees 512B-granular sequential streams (page-friendly)
//    instead of 128B slivers.
//  - W in smem as 16 planes wz[(j*4+p)*512 + kq] = (W[2p][4kq+j],W[2p+1][4kq+j]);
//    lane reads kq = kg*32+lane -> stride-8B conflict-free LDS.64, shared
//    across the 4 tokens of the pass.
//  - f32x2 accumulation, butterfly shuffle reduce, in-register softmax+top2,
//    direct stores. No barriers after W staging.

#define D_MODEL  2048
#define NEXP     8
#define THREADS  512
#define NWARP    16
#define NKG      16                  // k-groups of 128 floats

typedef unsigned long long u64;

__device__ __forceinline__ u64 splat2(float v) {
    u64 r; asm("mov.b64 %0, {%1, %1};" : "=l"(r) : "f"(v)); return r;
}
__device__ __forceinline__ void ffma2(u64& a, u64 x, u64 w) {
    asm("fma.rn.f32x2 %0, %1, %2, %0;" : "+l"(a) : "l"(x), "l"(w));
}
__device__ __forceinline__ void add2(u64& a, u64 o) {
    asm("add.rn.f32x2 %0, %0, %1;" : "+l"(a) : "l"(o));
}

__global__ __launch_bounds__(THREADS, 1)
void top2_router_kernel(const float* __restrict__ x,
                        const float* __restrict__ W,
                        const float* __restrict__ b,
                        float* __restrict__ out,
                        int n_tok)
{
    extern __shared__ u64 wz[];                 // 16 planes * 512 u64 = 64 KB

    const int tid  = threadIdx.x;
    const int w    = tid >> 5;
    const int lane = tid & 31;

    // ---- stage W planes: wz[(j*4+p)*512 + kq] = (W[2p][4kq+j], W[2p+1][4kq+j])
    #pragma unroll
    for (int i = 0; i < 8192 / THREADS; ++i) {  // 16
        int q     = tid + i * THREADS;          // 0..8191
        int plane = q >> 9;
        int kq    = q & 511;
        int j     = plane >> 2;
        int p     = plane & 3;
        int k     = 4 * kq + j;
        float lo  = W[(2 * p) * D_MODEL + k];
        float hi  = W[(2 * p + 1) * D_MODEL + k];
        u64 v; asm("mov.b64 %0, {%1, %2};" : "=l"(v) : "f"(lo), "f"(hi));
        wz[q] = v;
    }
    __syncthreads();                            // only barrier in the kernel

    // balanced token range (units of 8 tokens)
    const int G     = gridDim.x;
    const int units = n_tok >> 3;
    const int s8    = (int)(((long long)blockIdx.x       * units) / G);
    const int e8    = (int)(((long long)(blockIdx.x + 1) * units) / G);
    const int tokenBase = s8 * 8;
    const int ntok_b    = (e8 - s8) * 8;        // <= 112 for G >= 152
    const int npass     = ntok_b >> 2;          // 4-token passes

    for (int pass = w; pass < npass; pass += NWARP) {
        const int tok0 = tokenBase + pass * 4;
        const float* rp0 = x + (size_t)(tok0 + 0) * D_MODEL + 4 * lane;
        const float* rp1 = rp0 + D_MODEL;
        const float* rp2 = rp1 + D_MODEL;
        const float* rp3 = rp2 + D_MODEL;

        u64 acc[4][4];
        #pragma unroll
        for (int t = 0; t < 4; ++t)
            #pragma unroll
            for (int p = 0; p < 4; ++p) acc[t][p] = 0ull;

        float4 xc0 = *reinterpret_cast<const float4*>(rp0);
        float4 xc1 = *reinterpret_cast<const float4*>(rp1);
        float4 xc2 = *reinterpret_cast<const float4*>(rp2);
        float4 xc3 = *reinterpret_cast<const float4*>(rp3);

        #pragma unroll 1
        for (int kg = 0; kg < NKG; ++kg) {
            float4 xn0, xn1, xn2, xn3;
            if (kg + 1 < NKG) {
                const int off = (kg + 1) * 128;
                xn0 = *reinterpret_cast<const float4*>(rp0 + off);
                xn1 = *reinterpret_cast<const float4*>(rp1 + off);
                xn2 = *reinterpret_cast<const float4*>(rp2 + off);
                xn3 = *reinterpret_cast<const float4*>(rp3 + off);
            }
            const int idx = kg * 32 + lane;

            #pragma unroll
            for (int j = 0; j < 4; ++j) {
                u64 w0 = wz[(j * 4 + 0) * 512 + idx];
                u64 w1 = wz[(j * 4 + 1) * 512 + idx];
                u64 w2 = wz[(j * 4 + 2) * 512 + idx];
                u64 w3 = wz[(j * 4 + 3) * 512 + idx];
                #pragma unroll
                for (int t = 0; t < 4; ++t) {
                    const float4& xv = (t == 0) ? xc0 : (t == 1) ? xc1
                                     : (t == 2) ? xc2 : xc3;
                    float xk = (j == 0) ? xv.x : (j == 1) ? xv.y
                             : (j == 2) ? xv.z : xv.w;
                    u64 xx = splat2(xk);
                    ffma2(acc[t][0], xx, w0);
                    ffma2(acc[t][1], xx, w1);
                    ffma2(acc[t][2], xx, w2);
                    ffma2(acc[t][3], xx, w3);
                }
            }
            if (kg + 1 < NKG) { xc0 = xn0; xc1 = xn1; xc2 = xn2; xc3 = xn3; }
        }

        // ---- butterfly reduction across 32 lanes
        #pragma unroll
        for (int off = 16; off > 0; off >>= 1) {
            #pragma unroll
            for (int t = 0; t < 4; ++t)
                #pragma unroll
                for (int p = 0; p < 4; ++p) {
                    u64 o = __shfl_xor_sync(0xffffffffu, acc[t][p], off);
                    add2(acc[t][p], o);
                }
        }

        // ---- lanes 0..3: softmax + stable top2 for token tok0+lane
        if (lane < 4) {
            const int g = tok0 + lane;
            float gv[NEXP];
            #pragma unroll
            for (int p = 0; p < 4; ++p) {
                float lo, hi;
                asm("mov.b64 {%0, %1}, %2;" : "=f"(lo), "=f"(hi) : "l"(acc[lane][p]));
                gv[2 * p]     = lo + b[2 * p];
                gv[2 * p + 1] = hi + b[2 * p + 1];
            }
            float mx = -INFINITY;
            #pragma unroll
            for (int e = 0; e < NEXP; ++e) mx = fmaxf(mx, gv[e]);
            float ssum = 0.f;
            #pragma unroll
            for (int e = 0; e < NEXP; ++e) {
                gv[e] = __expf(gv[e] - mx);
                ssum += gv[e];
            }
            float inv = 1.f / ssum;
            #pragma unroll
            for (int e = 0; e < NEXP; ++e) gv[e] *= inv;

            float* gate_out = out + (size_t)n_tok * 4;
            float4 g0 = make_float4(gv[0], gv[1], gv[2], gv[3]);
            float4 g1 = make_float4(gv[4], gv[5], gv[6], gv[7]);
            *reinterpret_cast<float4*>(gate_out + (size_t)g * NEXP)     = g0;
            *reinterpret_cast<float4*>(gate_out + (size_t)g * NEXP + 4) = g1;

            int i1 = 0; float v1 = gv[0];
            #pragma unroll
            for (int e = 1; e < NEXP; ++e)
                if (gv[e] > v1) { v1 = gv[e]; i1 = e; }
            int i2 = -1; float v2 = -INFINITY;
            #pragma unroll
            for (int e = 0; e < NEXP; ++e)
                if (e != i1 && gv[e] > v2) { v2 = gv[e]; i2 = e; }

            *reinterpret_cast<float2*>(out + (size_t)g * 2) = make_float2(v1, v2);
            float* idx_out = out + (size_t)n_tok * 2;
            *reinterpret_cast<float2*>(idx_out + (size_t)g * 2) =
                make_float2((float)i1, (float)i2);
        }
    }
}

extern "C" void kernel_launch(void* const* d_in, const int* in_sizes, int n_in,
                              void* d_out, int out_size)
{
    const float* x = (const float*)d_in[0];
    const float* W = (const float*)d_in[1];
    const float* b = (const float*)d_in[2];
    float* out = (float*)d_out;

    const int n_tok = in_sizes[0] / D_MODEL;     // 16384
    const int smem_bytes = 8192 * (int)sizeof(u64);   // 64 KB

    static int nsm = 0;
    if (nsm == 0) {
        cudaDeviceProp prop;
        cudaGetDeviceProperties(&prop, 0);
        nsm = prop.multiProcessorCount;          // 152 on GB300
        cudaFuncSetAttribute(top2_router_kernel,
                             cudaFuncAttributeMaxDynamicSharedMemorySize, smem_bytes);
    }

    top2_router_kernel<<<nsm, THREADS, smem_bytes>>>(x, W, b, out, n_tok);
}

// round 11
// speedup vs baseline: 1.1072x; 1.1052x over previous
#include <cuda_runtime.h>
#include <cuda.h>
#include <math.h>

// Top2Router: x[16384,2048] fp32, W[8,2048], b[8]
// out (fp32 concat): top2_val[N*2] | top2_idx[N*2] | gate[N*8]
//
// R7 TMA kernel, edge-optimized (fixed):
//  - TMA chunks 0..2 issued BEFORE W staging (DRAM busy immediately)
//  - unit-1 balanced token ranges (107/108 rows), smem layout padded to
//    HIPAD=112 rows/tile so every TMA dst stays 1024B-aligned (SW128 req).
//  - 5-stage mbarrier ring, prefetch distance 3, one bar.sync per chunk.

#define D_MODEL  2048
#define NEXP     8
#define KCHUNK   64
#define NCHUNK   (D_MODEL / KCHUNK)   // 32
#define NSTAGE   5
#define THREADS  512
#define NWARP    16
#define HIPAD    112                   // layout rows per tile (mult of 8)
#define TILE_F   (32 * HIPAD)          // floats per tile  (3584)
#define STAGE_F  (2 * TILE_F)          // floats per stage (7168)

typedef unsigned long long u64;

__device__ __forceinline__ void mbar_init(unsigned mb, unsigned count) {
    asm volatile("mbarrier.init.shared.b64 [%0], %1;" :: "r"(mb), "r"(count) : "memory");
}
__device__ __forceinline__ void mbar_expect_tx(unsigned mb, unsigned bytes) {
    asm volatile("mbarrier.arrive.expect_tx.shared.b64 _, [%0], %1;"
                 :: "r"(mb), "r"(bytes) : "memory");
}
__device__ __forceinline__ void mbar_wait(unsigned mb, unsigned parity) {
    asm volatile(
        "{\n\t.reg .pred P;\n"
        "W_%=:\n\t"
        "mbarrier.try_wait.parity.acquire.cta.shared::cta.b64 P, [%0], %1, 0x989680;\n\t"
        "@P bra D_%=;\n\t"
        "bra W_%=;\n"
        "D_%=:\n\t}"
        :: "r"(mb), "r"(parity) : "memory");
}
__device__ __forceinline__ void tma2d(unsigned dst, const CUtensorMap* map,
                                      int c0, int c1, unsigned mb) {
    asm volatile(
        "cp.async.bulk.tensor.2d.shared::cta.global.tile.mbarrier::complete_tx::bytes "
        "[%0], [%1, {%2, %3}], [%4];"
        :: "r"(dst), "l"(map), "r"(c0), "r"(c1), "r"(mb) : "memory");
}

__global__ __launch_bounds__(THREADS, 1)
void top2_router_kernel(const __grid_constant__ CUtensorMap mapHi,
                        const __grid_constant__ CUtensorMap mapLo,
                        const float* __restrict__ W,
                        const float* __restrict__ b,
                        float* __restrict__ out,
                        int n_tok, int hi)
{
    extern __shared__ float smem[];
    float* ring = smem;                          // 5 * 7168 floats (aligned)
    float* wt   = smem + NSTAGE * STAGE_F;       // 16384 floats

    const unsigned smem_u32 = (unsigned)__cvta_generic_to_shared(smem);
    const unsigned ring_u32 = smem_u32;
    const unsigned mbar0    = smem_u32 + (unsigned)(NSTAGE * STAGE_F + 16384) * 4u;
    const unsigned stageBytes = (unsigned)STAGE_F * 4u;
    const unsigned tileBytes  = (unsigned)TILE_F * 4u;

    const int tid  = threadIdx.x;
    const int w    = tid >> 5;
    const int lane = tid & 31;

    // unit-1 balanced token range
    const int G     = gridDim.x;
    const int tokenBase = (int)(((long long)blockIdx.x       * n_tok) / G);
    const int tokenEnd  = (int)(((long long)(blockIdx.x + 1) * n_tok) / G);
    const int ntok_b    = tokenEnd - tokenBase;  // hi or hi-1

    const CUtensorMap* mp = (ntok_b == hi) ? &mapHi : &mapLo;
    const unsigned chunkBytes = (unsigned)ntok_b * 256u;   // 2 tiles * ntok_b * 128B

    // ---- FIRST: kick off TMA so DRAM is busy during W staging
    if (tid == 0) {
        #pragma unroll
        for (int s = 0; s < NSTAGE; ++s) mbar_init(mbar0 + s * 8, 1);
        asm volatile("fence.proxy.async.shared::cta;" ::: "memory");
        #pragma unroll
        for (int c = 0; c < 3; ++c) {
            unsigned mb  = mbar0 + (c % NSTAGE) * 8;
            unsigned dst = ring_u32 + (unsigned)(c % NSTAGE) * stageBytes;
            mbar_expect_tx(mb, chunkBytes);
            tma2d(dst,             mp, c * KCHUNK,      tokenBase, mb);
            tma2d(dst + tileBytes, mp, c * KCHUNK + 32, tokenBase, mb);
        }
    }

    // ---- stage W transposed: wt[k*8+e] = W[e*2048+k]
    #pragma unroll
    for (int i = 0; i < (D_MODEL * NEXP) / THREADS; ++i) {   // 32
        int idx = tid + i * THREADS;
        int e = idx >> 11;
        int k = idx & (D_MODEL - 1);
        wt[k * NEXP + e] = W[idx];
    }
    __syncthreads();

    const u64* wt64 = reinterpret_cast<const u64*>(wt);

    u64 acc[4][4];
    #pragma unroll
    for (int t = 0; t < 4; ++t)
        #pragma unroll
        for (int p = 0; p < 4; ++p) acc[t][p] = 0ull;

    const int ws7    = w & 7;
    const int tsel   = (w >> 3);                 // tile 0/1 (k<32 / k>=32)
    const int tokLim = ntok_b - 1;

    for (int c = 0; c < NCHUNK; ++c) {
        if (tid == 0 && c + 3 < NCHUNK) {
            int cc = c + 3;
            unsigned mb  = mbar0 + (cc % NSTAGE) * 8;
            unsigned dst = ring_u32 + (unsigned)(cc % NSTAGE) * stageBytes;
            mbar_expect_tx(mb, chunkBytes);
            tma2d(dst,             mp, cc * KCHUNK,      tokenBase, mb);
            tma2d(dst + tileBytes, mp, cc * KCHUNK + 32, tokenBase, mb);
        }
        mbar_wait(mbar0 + (c % NSTAGE) * 8, (unsigned)((c / NSTAGE) & 1));
        __syncthreads();

        const float* tile = ring + (c % NSTAGE) * STAGE_F + tsel * TILE_F;

        float4 xv[4];
        #pragma unroll
        for (int t = 0; t < 4; ++t) {
            int tok = lane + t * 32;
            int tokc = tok > tokLim ? tokLim : tok;
            xv[t] = reinterpret_cast<const float4*>(tile + tokc * 32)
                        [ws7 ^ (tokc & 7)];
        }

        #pragma unroll
        for (int j = 0; j < 4; ++j) {
            int kg = c * KCHUNK + w * 4 + j;
            u64 wp0 = wt64[kg * 4 + 0];
            u64 wp1 = wt64[kg * 4 + 1];
            u64 wp2 = wt64[kg * 4 + 2];
            u64 wp3 = wt64[kg * 4 + 3];
            #pragma unroll
            for (int t = 0; t < 4; ++t) {
                float xk = (j == 0) ? xv[t].x : (j == 1) ? xv[t].y
                         : (j == 2) ? xv[t].z : xv[t].w;
                u64 xx;
                asm("mov.b64 %0, {%1, %1};" : "=l"(xx) : "f"(xk));
                asm("fma.rn.f32x2 %0, %1, %2, %0;" : "+l"(acc[t][0]) : "l"(xx), "l"(wp0));
                asm("fma.rn.f32x2 %0, %1, %2, %0;" : "+l"(acc[t][1]) : "l"(xx), "l"(wp1));
                asm("fma.rn.f32x2 %0, %1, %2, %0;" : "+l"(acc[t][2]) : "l"(xx), "l"(wp2));
                asm("fma.rn.f32x2 %0, %1, %2, %0;" : "+l"(acc[t][3]) : "l"(xx), "l"(wp3));
            }
        }
    }
    __syncthreads();

    // ---- cross-warp reduction (reuse ring)
    float2* red = reinterpret_cast<float2*>(ring);
    #pragma unroll
    for (int t = 0; t < 4; ++t) {
        int tok = lane + t * 32;
        #pragma unroll
        for (int p = 0; p < 4; ++p) {
            float lo, hv;
            asm("mov.b64 {%0, %1}, %2;" : "=f"(lo), "=f"(hv) : "l"(acc[t][p]));
            red[(w * 128 + tok) * 4 + p] = make_float2(lo, hv);
        }
    }
    __syncthreads();

    float* lgs = ring + 16384;
    {
        int tok = tid >> 2;
        int p   = tid & 3;
        float2 s = make_float2(0.f, 0.f);
        #pragma unroll
        for (int ww = 0; ww < NWARP; ++ww) {
            float2 v = red[(ww * 128 + tok) * 4 + p];
            s.x += v.x; s.y += v.y;
        }
        s.x += b[2 * p];
        s.y += b[2 * p + 1];
        reinterpret_cast<float2*>(lgs)[tok * 4 + p] = s;
    }
    __syncthreads();

    // ---- per-token softmax + stable top2
    if (tid < ntok_b) {
        const int g = tokenBase + tid;
        float gv[NEXP];
        float mx = -INFINITY;
        #pragma unroll
        for (int e = 0; e < NEXP; ++e) {
            gv[e] = lgs[tid * NEXP + e];
            mx = fmaxf(mx, gv[e]);
        }
        float ssum = 0.f;
        #pragma unroll
        for (int e = 0; e < NEXP; ++e) {
            gv[e] = __expf(gv[e] - mx);
            ssum += gv[e];
        }
        float inv = 1.f / ssum;
        #pragma unroll
        for (int e = 0; e < NEXP; ++e) gv[e] *= inv;

        float* gate_out = out + (size_t)n_tok * 4;
        float4 g0 = make_float4(gv[0], gv[1], gv[2], gv[3]);
        float4 g1 = make_float4(gv[4], gv[5], gv[6], gv[7]);
        *reinterpret_cast<float4*>(gate_out + (size_t)g * NEXP)     = g0;
        *reinterpret_cast<float4*>(gate_out + (size_t)g * NEXP + 4) = g1;

        int i1 = 0; float v1 = gv[0];
        #pragma unroll
        for (int e = 1; e < NEXP; ++e)
            if (gv[e] > v1) { v1 = gv[e]; i1 = e; }
        int i2 = -1; float v2 = -INFINITY;
        #pragma unroll
        for (int e = 0; e < NEXP; ++e)
            if (e != i1 && gv[e] > v2) { v2 = gv[e]; i2 = e; }

        *reinterpret_cast<float2*>(out + (size_t)g * 2) = make_float2(v1, v2);
        float* idx_out = out + (size_t)n_tok * 2;
        *reinterpret_cast<float2*>(idx_out + (size_t)g * 2) =
            make_float2((float)i1, (float)i2);
    }
}

// ---------------------------------------------------------------------------

typedef CUresult (*EncodeTiledFn)(
    CUtensorMap*, CUtensorMapDataType, cuuint32_t, void*,
    const cuuint64_t*, const cuuint64_t*, const cuuint32_t*, const cuuint32_t*,
    CUtensorMapInterleave, CUtensorMapSwizzle, CUtensorMapL2promotion,
    CUtensorMapFloatOOBfill);

static CUtensorMap g_mapHi, g_mapLo;
static const void* g_last_x = nullptr;
static int g_nsm = 0, g_hi = 0, g_smem = 0;

static void build_maps(const float* x, int n_tok, int hi, int lo)
{
    EncodeTiledFn enc = nullptr;
    cudaDriverEntryPointQueryResult qr;
    cudaGetDriverEntryPoint("cuTensorMapEncodeTiled", (void**)&enc,
                            cudaEnableDefault, &qr);
    cuuint64_t dims[2]    = {(cuuint64_t)D_MODEL, (cuuint64_t)n_tok};
    cuuint64_t strides[1] = {(cuuint64_t)D_MODEL * 4};
    cuuint32_t elem[2]    = {1, 1};
    cuuint32_t boxH[2]    = {32, (cuuint32_t)hi};
    cuuint32_t boxL[2]    = {32, (cuuint32_t)lo};
    enc(&g_mapHi, CU_TENSOR_MAP_DATA_TYPE_FLOAT32, 2, (void*)x,
        dims, strides, boxH, elem,
        CU_TENSOR_MAP_INTERLEAVE_NONE, CU_TENSOR_MAP_SWIZZLE_128B,
        CU_TENSOR_MAP_L2_PROMOTION_L2_128B, CU_TENSOR_MAP_FLOAT_OOB_FILL_NONE);
    enc(&g_mapLo, CU_TENSOR_MAP_DATA_TYPE_FLOAT32, 2, (void*)x,
        dims, strides, boxL, elem,
        CU_TENSOR_MAP_INTERLEAVE_NONE, CU_TENSOR_MAP_SWIZZLE_128B,
        CU_TENSOR_MAP_L2_PROMOTION_L2_128B, CU_TENSOR_MAP_FLOAT_OOB_FILL_NONE);
}

extern "C" void kernel_launch(void* const* d_in, const int* in_sizes, int n_in,
                              void* d_out, int out_size)
{
    const float* x = (const float*)d_in[0];
    const float* W = (const float*)d_in[1];
    const float* b = (const float*)d_in[2];
    float* out = (float*)d_out;

    const int n_tok = in_sizes[0] / D_MODEL;     // 16384

    if (g_nsm == 0) {
        cudaDeviceProp prop;
        cudaGetDeviceProperties(&prop, 0);
        g_nsm = prop.multiProcessorCount;        // 152 on GB300
        g_hi = (n_tok + g_nsm - 1) / g_nsm;      // 108
        g_smem = (NSTAGE * STAGE_F + 16384) * 4 + 64;   // ~208.9 KB
        cudaFuncSetAttribute(top2_router_kernel,
                             cudaFuncAttributeMaxDynamicSharedMemorySize, g_smem);
        build_maps(x, n_tok, g_hi, g_hi - 1);
        g_last_x = x;
    } else if (g_last_x != x) {
        build_maps(x, n_tok, g_hi, g_hi - 1);
        g_last_x = x;
    }

    top2_router_kernel<<<g_nsm, THREADS, g_smem>>>(g_mapHi, g_mapLo,
                                                   W, b, out, n_tok, g_hi);
}

// round 14
// speedup vs baseline: 1.2024x; 1.0860x over previous
#include <cuda_runtime.h>
#include <cuda.h>
#include <math.h>

// Top2Router: x[16384,2048] fp32, W[8,2048], b[8]
// out (fp32 concat): top2_val[N*2] | top2_idx[N*2] | gate[N*8]
//
// R11 TMA kernel (proven) + distance-4 prefetch via post-barrier issue:
//  - TMA chunks 0..3 issued in prologue (0..2 before W staging).
//  - Per chunk: wait full[c]; __syncthreads; tid0 issues chunk c+4 into
//    slot (c+4)%5 = (c-1)%5 (safe: barrier guarantees all warps finished
//    reading chunk c-1); compute.
//  - unit-1 balanced ranges, HIPAD=112 smem layout (1024B-aligned TMA dsts).

#define D_MODEL  2048
#define NEXP     8
#define KCHUNK   64
#define NCHUNK   (D_MODEL / KCHUNK)   // 32
#define NSTAGE   5
#define THREADS  512
#define NWARP    16
#define HIPAD    112                   // layout rows per tile (mult of 8)
#define TILE_F   (32 * HIPAD)          // floats per tile  (3584)
#define STAGE_F  (2 * TILE_F)          // floats per stage (7168)

typedef unsigned long long u64;

__device__ __forceinline__ void mbar_init(unsigned mb, unsigned count) {
    asm volatile("mbarrier.init.shared.b64 [%0], %1;" :: "r"(mb), "r"(count) : "memory");
}
__device__ __forceinline__ void mbar_expect_tx(unsigned mb, unsigned bytes) {
    asm volatile("mbarrier.arrive.expect_tx.shared.b64 _, [%0], %1;"
                 :: "r"(mb), "r"(bytes) : "memory");
}
__device__ __forceinline__ void mbar_wait(unsigned mb, unsigned parity) {
    asm volatile(
        "{\n\t.reg .pred P;\n"
        "W_%=:\n\t"
        "mbarrier.try_wait.parity.acquire.cta.shared::cta.b64 P, [%0], %1, 0x989680;\n\t"
        "@P bra D_%=;\n\t"
        "bra W_%=;\n"
        "D_%=:\n\t}"
        :: "r"(mb), "r"(parity) : "memory");
}
__device__ __forceinline__ void tma2d(unsigned dst, const CUtensorMap* map,
                                      int c0, int c1, unsigned mb) {
    asm volatile(
        "cp.async.bulk.tensor.2d.shared::cta.global.tile.mbarrier::complete_tx::bytes "
        "[%0], [%1, {%2, %3}], [%4];"
        :: "r"(dst), "l"(map), "r"(c0), "r"(c1), "r"(mb) : "memory");
}

__global__ __launch_bounds__(THREADS, 1)
void top2_router_kernel(const __grid_constant__ CUtensorMap mapHi,
                        const __grid_constant__ CUtensorMap mapLo,
                        const float* __restrict__ W,
                        const float* __restrict__ b,
                        float* __restrict__ out,
                        int n_tok, int hi)
{
    extern __shared__ float smem[];
    float* ring = smem;                          // 5 * 7168 floats (aligned)
    float* wt   = smem + NSTAGE * STAGE_F;       // 16384 floats

    const unsigned smem_u32 = (unsigned)__cvta_generic_to_shared(smem);
    const unsigned ring_u32 = smem_u32;
    const unsigned mbar0    = smem_u32 + (unsigned)(NSTAGE * STAGE_F + 16384) * 4u;
    const unsigned stageBytes = (unsigned)STAGE_F * 4u;
    const unsigned tileBytes  = (unsigned)TILE_F * 4u;

    const int tid  = threadIdx.x;
    const int w    = tid >> 5;
    const int lane = tid & 31;

    // unit-1 balanced token range
    const int G     = gridDim.x;
    const int tokenBase = (int)(((long long)blockIdx.x       * n_tok) / G);
    const int tokenEnd  = (int)(((long long)(blockIdx.x + 1) * n_tok) / G);
    const int ntok_b    = tokenEnd - tokenBase;  // hi or hi-1

    const CUtensorMap* mp = (ntok_b == hi) ? &mapHi : &mapLo;
    const unsigned chunkBytes = (unsigned)ntok_b * 256u;   // 2 tiles * ntok_b * 128B

    // ---- FIRST: kick off TMA so DRAM is busy during W staging
    if (tid == 0) {
        #pragma unroll
        for (int s = 0; s < NSTAGE; ++s) mbar_init(mbar0 + s * 8, 1);
        asm volatile("fence.proxy.async.shared::cta;" ::: "memory");
        #pragma unroll
        for (int c = 0; c < 3; ++c) {
            unsigned mb  = mbar0 + (c % NSTAGE) * 8;
            unsigned dst = ring_u32 + (unsigned)(c % NSTAGE) * stageBytes;
            mbar_expect_tx(mb, chunkBytes);
            tma2d(dst,             mp, c * KCHUNK,      tokenBase, mb);
            tma2d(dst + tileBytes, mp, c * KCHUNK + 32, tokenBase, mb);
        }
    }

    // ---- stage W transposed: wt[k*8+e] = W[e*2048+k]
    #pragma unroll
    for (int i = 0; i < (D_MODEL * NEXP) / THREADS; ++i) {   // 32
        int idx = tid + i * THREADS;
        int e = idx >> 11;
        int k = idx & (D_MODEL - 1);
        wt[k * NEXP + e] = W[idx];
    }
    __syncthreads();

    // issue chunk 3 (slot 3 untouched; completes the 4-deep prologue)
    if (tid == 0) {
        unsigned mb  = mbar0 + 3 * 8;
        unsigned dst = ring_u32 + 3u * stageBytes;
        mbar_expect_tx(mb, chunkBytes);
        tma2d(dst,             mp, 3 * KCHUNK,      tokenBase, mb);
        tma2d(dst + tileBytes, mp, 3 * KCHUNK + 32, tokenBase, mb);
    }

    const u64* wt64 = reinterpret_cast<const u64*>(wt);

    u64 acc[4][4];
    #pragma unroll
    for (int t = 0; t < 4; ++t)
        #pragma unroll
        for (int p = 0; p < 4; ++p) acc[t][p] = 0ull;

    const int ws7    = w & 7;
    const int tsel   = (w >> 3);                 // tile 0/1 (k<32 / k>=32)
    const int tokLim = ntok_b - 1;

    for (int c = 0; c < NCHUNK; ++c) {
        mbar_wait(mbar0 + (c % NSTAGE) * 8, (unsigned)((c / NSTAGE) & 1));
        __syncthreads();   // all warps done chunk c-1 -> slot (c+4)%5 free

        if (tid == 0 && c + 4 < NCHUNK) {
            int cc = c + 4;
            unsigned mb  = mbar0 + (cc % NSTAGE) * 8;
            unsigned dst = ring_u32 + (unsigned)(cc % NSTAGE) * stageBytes;
            mbar_expect_tx(mb, chunkBytes);
            tma2d(dst,             mp, cc * KCHUNK,      tokenBase, mb);
            tma2d(dst + tileBytes, mp, cc * KCHUNK + 32, tokenBase, mb);
        }

        const float* tile = ring + (c % NSTAGE) * STAGE_F + tsel * TILE_F;

        float4 xv[4];
        #pragma unroll
        for (int t = 0; t < 4; ++t) {
            int tok = lane + t * 32;
            int tokc = tok > tokLim ? tokLim : tok;
            xv[t] = reinterpret_cast<const float4*>(tile + tokc * 32)
                        [ws7 ^ (tokc & 7)];
        }

        #pragma unroll
        for (int j = 0; j < 4; ++j) {
            int kg = c * KCHUNK + w * 4 + j;
            u64 wp0 = wt64[kg * 4 + 0];
            u64 wp1 = wt64[kg * 4 + 1];
            u64 wp2 = wt64[kg * 4 + 2];
            u64 wp3 = wt64[kg * 4 + 3];
            #pragma unroll
            for (int t = 0; t < 4; ++t) {
                float xk = (j == 0) ? xv[t].x : (j == 1) ? xv[t].y
                         : (j == 2) ? xv[t].z : xv[t].w;
                u64 xx;
                asm("mov.b64 %0, {%1, %1};" : "=l"(xx) : "f"(xk));
                asm("fma.rn.f32x2 %0, %1, %2, %0;" : "+l"(acc[t][0]) : "l"(xx), "l"(wp0));
                asm("fma.rn.f32x2 %0, %1, %2, %0;" : "+l"(acc[t][1]) : "l"(xx), "l"(wp1));
                asm("fma.rn.f32x2 %0, %1, %2, %0;" : "+l"(acc[t][2]) : "l"(xx), "l"(wp2));
                asm("fma.rn.f32x2 %0, %1, %2, %0;" : "+l"(acc[t][3]) : "l"(xx), "l"(wp3));
            }
        }
    }
    __syncthreads();

    // ---- cross-warp reduction (reuse ring)
    float2* red = reinterpret_cast<float2*>(ring);
    #pragma unroll
    for (int t = 0; t < 4; ++t) {
        int tok = lane + t * 32;
        #pragma unroll
        for (int p = 0; p < 4; ++p) {
            float lo, hv;
            asm("mov.b64 {%0, %1}, %2;" : "=f"(lo), "=f"(hv) : "l"(acc[t][p]));
            red[(w * 128 + tok) * 4 + p] = make_float2(lo, hv);
        }
    }
    __syncthreads();

    float* lgs = ring + 16384;
    {
        int tok = tid >> 2;
        int p   = tid & 3;
        float2 s = make_float2(0.f, 0.f);
        #pragma unroll
        for (int ww = 0; ww < NWARP; ++ww) {
            float2 v = red[(ww * 128 + tok) * 4 + p];
            s.x += v.x; s.y += v.y;
        }
        s.x += b[2 * p];
        s.y += b[2 * p + 1];
        reinterpret_cast<float2*>(lgs)[tok * 4 + p] = s;
    }
    __syncthreads();

    // ---- per-token softmax + stable top2
    if (tid < ntok_b) {
        const int g = tokenBase + tid;
        float gv[NEXP];
        float mx = -INFINITY;
        #pragma unroll
        for (int e = 0; e < NEXP; ++e) {
            gv[e] = lgs[tid * NEXP + e];
            mx = fmaxf(mx, gv[e]);
        }
        float ssum = 0.f;
        #pragma unroll
        for (int e = 0; e < NEXP; ++e) {
            gv[e] = __expf(gv[e] - mx);
            ssum += gv[e];
        }
        float inv = 1.f / ssum;
        #pragma unroll
        for (int e = 0; e < NEXP; ++e) gv[e] *= inv;

        float* gate_out = out + (size_t)n_tok * 4;
        float4 g0 = make_float4(gv[0], gv[1], gv[2], gv[3]);
        float4 g1 = make_float4(gv[4], gv[5], gv[6], gv[7]);
        *reinterpret_cast<float4*>(gate_out + (size_t)g * NEXP)     = g0;
        *reinterpret_cast<float4*>(gate_out + (size_t)g * NEXP + 4) = g1;

        int i1 = 0; float v1 = gv[0];
        #pragma unroll
        for (int e = 1; e < NEXP; ++e)
            if (gv[e] > v1) { v1 = gv[e]; i1 = e; }
        int i2 = -1; float v2 = -INFINITY;
        #pragma unroll
        for (int e = 0; e < NEXP; ++e)
            if (e != i1 && gv[e] > v2) { v2 = gv[e]; i2 = e; }

        *reinterpret_cast<float2*>(out + (size_t)g * 2) = make_float2(v1, v2);
        float* idx_out = out + (size_t)n_tok * 2;
        *reinterpret_cast<float2*>(idx_out + (size_t)g * 2) =
            make_float2((float)i1, (float)i2);
    }
}

// ---------------------------------------------------------------------------

typedef CUresult (*EncodeTiledFn)(
    CUtensorMap*, CUtensorMapDataType, cuuint32_t, void*,
    const cuuint64_t*, const cuuint64_t*, const cuuint32_t*, const cuuint32_t*,
    CUtensorMapInterleave, CUtensorMapSwizzle, CUtensorMapL2promotion,
    CUtensorMapFloatOOBfill);

static CUtensorMap g_mapHi, g_mapLo;
static const void* g_last_x = nullptr;
static int g_nsm = 0, g_hi = 0, g_smem = 0;

static void build_maps(const float* x, int n_tok, int hi, int lo)
{
    EncodeTiledFn enc = nullptr;
    cudaDriverEntryPointQueryResult qr;
    cudaGetDriverEntryPoint("cuTensorMapEncodeTiled", (void**)&enc,
                            cudaEnableDefault, &qr);
    cuuint64_t dims[2]    = {(cuuint64_t)D_MODEL, (cuuint64_t)n_tok};
    cuuint64_t strides[1] = {(cuuint64_t)D_MODEL * 4};
    cuuint32_t elem[2]    = {1, 1};
    cuuint32_t boxH[2]    = {32, (cuuint32_t)hi};
    cuuint32_t boxL[2]    = {32, (cuuint32_t)lo};
    enc(&g_mapHi, CU_TENSOR_MAP_DATA_TYPE_FLOAT32, 2, (void*)x,
        dims, strides, boxH, elem,
        CU_TENSOR_MAP_INTERLEAVE_NONE, CU_TENSOR_MAP_SWIZZLE_128B,
        CU_TENSOR_MAP_L2_PROMOTION_L2_128B, CU_TENSOR_MAP_FLOAT_OOB_FILL_NONE);
    enc(&g_mapLo, CU_TENSOR_MAP_DATA_TYPE_FLOAT32, 2, (void*)x,
        dims, strides, boxL, elem,
        CU_TENSOR_MAP_INTERLEAVE_NONE, CU_TENSOR_MAP_SWIZZLE_128B,
        CU_TENSOR_MAP_L2_PROMOTION_L2_128B, CU_TENSOR_MAP_FLOAT_OOB_FILL_NONE);
}

extern "C" void kernel_launch(void* const* d_in, const int* in_sizes, int n_in,
                              void* d_out, int out_size)
{
    const float* x = (const float*)d_in[0];
    const float* W = (const float*)d_in[1];
    const float* b = (const float*)d_in[2];
    float* out = (float*)d_out;

    const int n_tok = in_sizes[0] / D_MODEL;     // 16384

    if (g_nsm == 0) {
        cudaDeviceProp prop;
        cudaGetDeviceProperties(&prop, 0);
        g_nsm = prop.multiProcessorCount;        // 152 on GB300
        g_hi = (n_tok + g_nsm - 1) / g_nsm;      // 108
        g_smem = (NSTAGE * STAGE_F + 16384) * 4 + 64;
        cudaFuncSetAttribute(top2_router_kernel,
                             cudaFuncAttributeMaxDynamicSharedMemorySize, g_smem);
        build_maps(x, n_tok, g_hi, g_hi - 1);
        g_last_x = x;
    } else if (g_last_x != x) {
        build_maps(x, n_tok, g_hi, g_hi - 1);
        g_last_x = x;
    }

    top2_router_kernel<<<g_nsm, THREADS, g_smem>>>(g_mapHi, g_mapLo,
                                                   W, b, out, n_tok, g_hi);
}